// round 4
// baseline (speedup 1.0000x reference)
#include <cuda_runtime.h>
#include <cuda_bf16.h>
#include <cstdint>
#include <cstddef>

#define TT 8192
#define EE 4096

// ---------------- scratch (device globals) ----------------------------------
__device__ __nv_bfloat16 g_tokH[(size_t)TT * EE];   // tokens hi; later out [E,T] hi
__device__ __nv_bfloat16 g_tokL[(size_t)TT * EE];
__device__ __nv_bfloat16 g_wtH[(size_t)EE * EE];    // W^T hi (Wq/Wk/Wv sequentially)
__device__ __nv_bfloat16 g_wtL[(size_t)EE * EE];
__device__ __nv_bfloat16 g_wpH[(size_t)TT * TT];    // Wp^T hi
__device__ __nv_bfloat16 g_wpL[(size_t)TT * TT];
__device__ __nv_bfloat16 g_qtH[(size_t)EE * TT];    // q^T [E,T]
__device__ __nv_bfloat16 g_qtL[(size_t)EE * TT];
__device__ __nv_bfloat16 g_ktH[(size_t)EE * TT];
__device__ __nv_bfloat16 g_ktL[(size_t)EE * TT];
__device__ __nv_bfloat16 g_vH[(size_t)TT * EE];     // v [T,E]
__device__ __nv_bfloat16 g_vL[(size_t)TT * EE];
__device__ float g_S[(size_t)EE * EE];              // logits fp32
__device__ __nv_bfloat16 g_attH[(size_t)EE * EE];
__device__ __nv_bfloat16 g_attL[(size_t)EE * EE];

// ---------------- helpers ---------------------------------------------------
__device__ __forceinline__ uint32_t s2u(const void* p) {
    uint32_t a;
    asm("{ .reg .u64 t; cvta.to.shared.u64 t, %1; cvt.u32.u64 %0, t; }"
        : "=r"(a) : "l"(p));
    return a;
}
__device__ __forceinline__ void cp16(uint32_t dst, const void* src) {
    asm volatile("cp.async.cg.shared.global [%0], [%1], 16;"
                 :: "r"(dst), "l"(src));
}
#define CP_COMMIT() asm volatile("cp.async.commit_group;" ::: "memory")
#define CP_WAIT1()  asm volatile("cp.async.wait_group 1;" ::: "memory")

#define LDSM4(r, a)                                                          \
    asm volatile("ldmatrix.sync.aligned.m8n8.x4.shared.b16 "                 \
                 "{%0,%1,%2,%3}, [%4];"                                      \
                 : "=r"((r)[0]), "=r"((r)[1]), "=r"((r)[2]), "=r"((r)[3])    \
                 : "r"(a))

#define MMA16816(c, a, b0, b1)                                               \
    asm volatile("mma.sync.aligned.m16n8k16.row.col.f32.bf16.bf16.f32 "      \
                 "{%0,%1,%2,%3}, {%4,%5,%6,%7}, {%8,%9}, {%0,%1,%2,%3};"     \
                 : "+f"((c)[0]), "+f"((c)[1]), "+f"((c)[2]), "+f"((c)[3])    \
                 : "r"((a)[0]), "r"((a)[1]), "r"((a)[2]), "r"((a)[3]),       \
                   "r"(b0), "r"(b1))

__device__ __forceinline__ __nv_bfloat16 bhi(float v) { return __float2bfloat16(v); }
__device__ __forceinline__ __nv_bfloat16 blo(float v, __nv_bfloat16 h) {
    return __float2bfloat16(v - __bfloat162float(h));
}

// ---------------- split-bf16 HMMA GEMM --------------------------------------
// C[M,N] = sum_k A[m,k]*B[n,k]; A,B bf16 hi/lo pairs, K-major.
// OUTM: 0 = fp32 out (Co), 1 = split bf16 out (Co=hi, Col=lo)
// BIASM: 0 none, 1 per-col (bias[n]), 2 per-row (bias[m])
#define BM 128
#define BN 256
#define BKT 32
#define PITCH 80
#define A_HL 10240          // 128 * 80
#define B_OFF 20480
#define B_HL 20480          // 256 * 80
#define STAGE 61440
#define NST 3

template <int OUTM, int BIASM>
__global__ __launch_bounds__(256, 1)
void gemm_mma(const __nv_bfloat16* __restrict__ Ah, const __nv_bfloat16* __restrict__ Al,
              const __nv_bfloat16* __restrict__ Bh, const __nv_bfloat16* __restrict__ Bl,
              void* __restrict__ Co, void* __restrict__ Col,
              const float* __restrict__ bias,
              int M, int N, int K)
{
    extern __shared__ char dsm[];
    const uint32_t sb = s2u(dsm);

    const int tid  = threadIdx.x;
    const int wid  = tid >> 5;
    const int lane = tid & 31;
    const int bm = blockIdx.y * BM;
    const int bn = blockIdx.x * BN;
    const int m0 = (wid >> 2) * 64;
    const int n0 = (wid & 3) * 64;
    const int kt = K / BKT;

    auto load_stage = [&](int slot, int tile) {
        const uint32_t base = sb + slot * STAGE;
        const int k0 = tile * BKT;
        #pragma unroll
        for (int j = 0; j < 12; j++) {
            int c = tid + j * 256;
            uint32_t dst;
            const __nv_bfloat16* src;
            if (c < 1024) {
                int hl = c >> 9, row = (c >> 2) & 127, ch = c & 3;
                dst = base + hl * A_HL + row * PITCH + ch * 16;
                const __nv_bfloat16* p = hl ? Al : Ah;
                src = p + (size_t)(bm + row) * K + k0 + ch * 8;
            } else {
                int cc = c - 1024;
                int hl = cc >> 10, row = (cc >> 2) & 255, ch = cc & 3;
                dst = base + B_OFF + hl * B_HL + row * PITCH + ch * 16;
                const __nv_bfloat16* p = hl ? Bl : Bh;
                src = p + (size_t)(bn + row) * K + k0 + ch * 8;
            }
            cp16(dst, src);
        }
    };

    float acc[4][8][4];
    #pragma unroll
    for (int mt = 0; mt < 4; mt++)
        #pragma unroll
        for (int nt = 0; nt < 8; nt++)
            #pragma unroll
            for (int r = 0; r < 4; r++) acc[mt][nt][r] = 0.f;

    const uint32_t rowA = (uint32_t)(m0 + (lane & 15)) * PITCH + ((lane >> 4) << 4);
    const int quad = lane >> 3, rl = lane & 7;
    const uint32_t rowB = (uint32_t)(n0 + ((quad >> 1) << 3) + rl) * PITCH
                        + ((quad & 1) << 4);

    // prefetch first two stages
    load_stage(0, 0); CP_COMMIT();
    if (kt > 1) load_stage(1, 1);
    CP_COMMIT();

    for (int i = 0; i < kt; i++) {
        CP_WAIT1();                 // stage i resident
        __syncthreads();            // visible to all; slot (i+2)%NST free
        const int nxt = i + NST - 1;
        if (nxt < kt) load_stage(nxt % NST, nxt);
        CP_COMMIT();

        const uint32_t base = sb + (i % NST) * STAGE;
        #pragma unroll
        for (int ks = 0; ks < 2; ks++) {
            uint32_t ah[4][4], al[4][4], bh[4][4], bl[4][4];
            const uint32_t ko = ks * 32;
            #pragma unroll
            for (int mt = 0; mt < 4; mt++)
                LDSM4(ah[mt], base + rowA + mt * (16 * PITCH) + ko);
            #pragma unroll
            for (int np = 0; np < 4; np++)
                LDSM4(bh[np], base + B_OFF + rowB + np * (16 * PITCH) + ko);
            #pragma unroll
            for (int mt = 0; mt < 4; mt++)
                LDSM4(al[mt], base + A_HL + rowA + mt * (16 * PITCH) + ko);
            #pragma unroll
            for (int np = 0; np < 4; np++)
                LDSM4(bl[np], base + B_OFF + B_HL + rowB + np * (16 * PITCH) + ko);
            #pragma unroll
            for (int mt = 0; mt < 4; mt++)
                #pragma unroll
                for (int nt = 0; nt < 8; nt++)
                    MMA16816(acc[mt][nt], ah[mt], bh[nt >> 1][(nt & 1) * 2],
                             bh[nt >> 1][(nt & 1) * 2 + 1]);
            #pragma unroll
            for (int mt = 0; mt < 4; mt++)
                #pragma unroll
                for (int nt = 0; nt < 8; nt++)
                    MMA16816(acc[mt][nt], ah[mt], bl[nt >> 1][(nt & 1) * 2],
                             bl[nt >> 1][(nt & 1) * 2 + 1]);
            #pragma unroll
            for (int mt = 0; mt < 4; mt++)
                #pragma unroll
                for (int nt = 0; nt < 8; nt++)
                    MMA16816(acc[mt][nt], al[mt], bh[nt >> 1][(nt & 1) * 2],
                             bh[nt >> 1][(nt & 1) * 2 + 1]);
        }
    }

    // ---- epilogue ----
    const int r1 = lane >> 2;
    const int cb = (lane & 3) * 2;
    float rbA[4], rbB[4];
    #pragma unroll
    for (int mt = 0; mt < 4; mt++) {
        if (BIASM == 2) {
            rbA[mt] = bias[bm + m0 + mt * 16 + r1];
            rbB[mt] = bias[bm + m0 + mt * 16 + r1 + 8];
        } else { rbA[mt] = 0.f; rbB[mt] = 0.f; }
    }
    #pragma unroll
    for (int nt = 0; nt < 8; nt++) {
        const int col = bn + n0 + nt * 8 + cb;
        float cb0 = 0.f, cb1 = 0.f;
        if (BIASM == 1) { cb0 = bias[col]; cb1 = bias[col + 1]; }
        #pragma unroll
        for (int mt = 0; mt < 4; mt++) {
            const int row = bm + m0 + mt * 16 + r1;
            float v0 = acc[mt][nt][0] + cb0 + rbA[mt];
            float v1 = acc[mt][nt][1] + cb1 + rbA[mt];
            float v2 = acc[mt][nt][2] + cb0 + rbB[mt];
            float v3 = acc[mt][nt][3] + cb1 + rbB[mt];
            if (OUTM == 0) {
                float* C = (float*)Co;
                *reinterpret_cast<float2*>(C + (size_t)row * N + col) =
                    make_float2(v0, v1);
                *reinterpret_cast<float2*>(C + (size_t)(row + 8) * N + col) =
                    make_float2(v2, v3);
            } else {
                __nv_bfloat16* H = (__nv_bfloat16*)Co;
                __nv_bfloat16* L = (__nv_bfloat16*)Col;
                __nv_bfloat162 h01, l01, h23, l23;
                h01.x = bhi(v0); h01.y = bhi(v1);
                l01.x = blo(v0, h01.x); l01.y = blo(v1, h01.y);
                h23.x = bhi(v2); h23.y = bhi(v3);
                l23.x = blo(v2, h23.x); l23.y = blo(v3, h23.y);
                *reinterpret_cast<__nv_bfloat162*>(H + (size_t)row * N + col) = h01;
                *reinterpret_cast<__nv_bfloat162*>(L + (size_t)row * N + col) = l01;
                *reinterpret_cast<__nv_bfloat162*>(H + (size_t)(row + 8) * N + col) = h23;
                *reinterpret_cast<__nv_bfloat162*>(L + (size_t)(row + 8) * N + col) = l23;
            }
        }
    }
}

// ---------------- split / transpose preps ----------------------------------
__global__ void split_kernel(const float* __restrict__ in,
                             __nv_bfloat16* __restrict__ oh,
                             __nv_bfloat16* __restrict__ ol, size_t n4)
{
    size_t i = (size_t)blockIdx.x * 256 + threadIdx.x;
    if (i >= n4) return;
    float4 v = reinterpret_cast<const float4*>(in)[i];
    __nv_bfloat16 h0 = bhi(v.x), h1 = bhi(v.y), h2 = bhi(v.z), h3 = bhi(v.w);
    __nv_bfloat162 H0; H0.x = h0; H0.y = h1;
    __nv_bfloat162 H1; H1.x = h2; H1.y = h3;
    __nv_bfloat162 L0; L0.x = blo(v.x, h0); L0.y = blo(v.y, h1);
    __nv_bfloat162 L1; L1.x = blo(v.z, h2); L1.y = blo(v.w, h3);
    reinterpret_cast<__nv_bfloat162*>(oh)[2 * i]     = H0;
    reinterpret_cast<__nv_bfloat162*>(oh)[2 * i + 1] = H1;
    reinterpret_cast<__nv_bfloat162*>(ol)[2 * i]     = L0;
    reinterpret_cast<__nv_bfloat162*>(ol)[2 * i + 1] = L1;
}

// in [R,C] fp32 -> oh/ol [C,R] bf16 (out[c][r] = in[r][c])
__global__ void splitT_kernel(const float* __restrict__ in,
                              __nv_bfloat16* __restrict__ oh,
                              __nv_bfloat16* __restrict__ ol, int R, int C)
{
    __shared__ float t[32][33];
    int x  = blockIdx.x * 32 + threadIdx.x;
    int y0 = blockIdx.y * 32;
    #pragma unroll
    for (int j = 0; j < 32; j += 8)
        t[threadIdx.y + j][threadIdx.x] = in[(size_t)(y0 + threadIdx.y + j) * C + x];
    __syncthreads();
    int ox  = y0 + threadIdx.x;
    int oy0 = blockIdx.x * 32;
    #pragma unroll
    for (int j = 0; j < 32; j += 8) {
        float v = t[threadIdx.x][threadIdx.y + j];
        __nv_bfloat16 h = bhi(v);
        size_t idx = (size_t)(oy0 + threadIdx.y + j) * R + ox;
        oh[idx] = h;
        ol[idx] = blo(v, h);
    }
}

// ---------------- softmax with fused split ---------------------------------
__global__ void softmax_split(const float* __restrict__ S,
                              __nv_bfloat16* __restrict__ oh,
                              __nv_bfloat16* __restrict__ ol, int n)
{
    const int tid = threadIdx.x;
    const float* p = S + (size_t)blockIdx.x * n;
    float v[16];
    float m = -3.4e38f;
    #pragma unroll
    for (int i = 0; i < 16; i++) {
        v[i] = p[tid + (i << 8)];
        m = fmaxf(m, v[i]);
    }
    __shared__ float red[8];
    #pragma unroll
    for (int o = 16; o > 0; o >>= 1)
        m = fmaxf(m, __shfl_xor_sync(0xffffffffu, m, o));
    if ((tid & 31) == 0) red[tid >> 5] = m;
    __syncthreads();
    float M = red[0];
    #pragma unroll
    for (int i = 1; i < 8; i++) M = fmaxf(M, red[i]);

    float s = 0.f;
    #pragma unroll
    for (int i = 0; i < 16; i++) {
        v[i] = expf(v[i] - M);
        s += v[i];
    }
    __syncthreads();
    #pragma unroll
    for (int o = 16; o > 0; o >>= 1)
        s += __shfl_xor_sync(0xffffffffu, s, o);
    if ((tid & 31) == 0) red[tid >> 5] = s;
    __syncthreads();
    float tot = 0.f;
    #pragma unroll
    for (int i = 0; i < 8; i++) tot += red[i];
    const float inv = 1.0f / tot;

    __nv_bfloat16* ph = oh + (size_t)blockIdx.x * n;
    __nv_bfloat16* pl = ol + (size_t)blockIdx.x * n;
    #pragma unroll
    for (int i = 0; i < 16; i++) {
        float w = v[i] * inv;
        __nv_bfloat16 h = bhi(w);
        ph[tid + (i << 8)] = h;
        pl[tid + (i << 8)] = blo(w, h);
    }
}

// ---------------- host ------------------------------------------------------
extern "C" void kernel_launch(void* const* d_in, const int* in_sizes, int n_in,
                              void* d_out, int out_size)
{
    (void)in_sizes; (void)n_in; (void)out_size;
    const float* tokens = (const float*)d_in[0];
    const float* Wq = (const float*)d_in[1];
    const float* bq = (const float*)d_in[2];
    const float* Wk = (const float*)d_in[3];
    const float* bk = (const float*)d_in[4];
    const float* Wv = (const float*)d_in[5];
    const float* bv = (const float*)d_in[6];
    const float* Wp = (const float*)d_in[7];
    const float* bp = (const float*)d_in[8];
    float* out = (float*)d_out;

    __nv_bfloat16 *tokH, *tokL, *wtH, *wtL, *wpH, *wpL;
    __nv_bfloat16 *qtH, *qtL, *ktH, *ktL, *vH, *vL, *attH, *attL;
    float *S;
    cudaGetSymbolAddress((void**)&tokH, g_tokH);
    cudaGetSymbolAddress((void**)&tokL, g_tokL);
    cudaGetSymbolAddress((void**)&wtH, g_wtH);
    cudaGetSymbolAddress((void**)&wtL, g_wtL);
    cudaGetSymbolAddress((void**)&wpH, g_wpH);
    cudaGetSymbolAddress((void**)&wpL, g_wpL);
    cudaGetSymbolAddress((void**)&qtH, g_qtH);
    cudaGetSymbolAddress((void**)&qtL, g_qtL);
    cudaGetSymbolAddress((void**)&ktH, g_ktH);
    cudaGetSymbolAddress((void**)&ktL, g_ktL);
    cudaGetSymbolAddress((void**)&vH, g_vH);
    cudaGetSymbolAddress((void**)&vL, g_vL);
    cudaGetSymbolAddress((void**)&attH, g_attH);
    cudaGetSymbolAddress((void**)&attL, g_attL);
    cudaGetSymbolAddress((void**)&S, g_S);

    const int T = TT, E = EE;
    const size_t TE4 = (size_t)T * E / 4;

    static bool attr_set = false;
    if (!attr_set) {
        cudaFuncSetAttribute(gemm_mma<0, 0>, cudaFuncAttributeMaxDynamicSharedMemorySize, NST * STAGE);
        cudaFuncSetAttribute(gemm_mma<0, 1>, cudaFuncAttributeMaxDynamicSharedMemorySize, NST * STAGE);
        cudaFuncSetAttribute(gemm_mma<1, 1>, cudaFuncAttributeMaxDynamicSharedMemorySize, NST * STAGE);
        cudaFuncSetAttribute(gemm_mma<1, 2>, cudaFuncAttributeMaxDynamicSharedMemorySize, NST * STAGE);
        cudaFuncSetAttribute(gemm_mma<1, 0>, cudaFuncAttributeMaxDynamicSharedMemorySize, NST * STAGE);
        attr_set = true;
    }
    const size_t smem = NST * STAGE;
    dim3 blkT(32, 8);

    // preps: split tokens; transpose+split Wp
    split_kernel<<<(unsigned)(TE4 / 256), 256>>>(tokens, tokH, tokL, TE4);
    splitT_kernel<<<dim3(T / 32, T / 32), blkT>>>(Wp, wpH, wpL, T, T);

    // q^T [E,T] = Wq^T(as A) x tokens(as B), row bias bq, split output
    splitT_kernel<<<dim3(E / 32, E / 32), blkT>>>(Wq, wtH, wtL, E, E);
    gemm_mma<1, 2><<<dim3(T / BN, E / BM), 256, smem>>>(
        wtH, wtL, tokH, tokL, qtH, qtL, bq, E, T, E);

    // k^T [E,T]
    splitT_kernel<<<dim3(E / 32, E / 32), blkT>>>(Wk, wtH, wtL, E, E);
    gemm_mma<1, 2><<<dim3(T / BN, E / BM), 256, smem>>>(
        wtH, wtL, tokH, tokL, ktH, ktL, bk, E, T, E);

    // v [T,E] = tokens x Wv^T(as B), col bias bv, split output
    splitT_kernel<<<dim3(E / 32, E / 32), blkT>>>(Wv, wtH, wtL, E, E);
    gemm_mma<1, 1><<<dim3(E / BN, T / BM), 256, smem>>>(
        tokH, tokL, wtH, wtL, vH, vL, bv, T, E, E);

    // logits S[E,E] = q^T k   (A=qt [E,T], B=kt [E,T], K=T), fp32 out
    gemm_mma<0, 0><<<dim3(E / BN, E / BM), 256, smem>>>(
        qtH, qtL, ktH, ktL, S, nullptr, nullptr, E, E, T);

    // softmax rows + fused split -> attH/attL
    softmax_split<<<E, 256>>>(S, attH, attL, E);

    // out [E,T] = att @ v^T  (A=att [E,E], B=v [T,E], K=E), split out -> tok bufs
    gemm_mma<1, 0><<<dim3(T / BN, E / BM), 256, smem>>>(
        attH, attL, vH, vL, tokH, tokL, nullptr, E, T, E);

    // result [E,T] = out @ Wp + bp  (A=out [E,T], B=Wp^T [T,T], K=T), fp32 out
    gemm_mma<0, 1><<<dim3(T / BN, E / BM), 256, smem>>>(
        tokH, tokL, wpH, wpL, out, nullptr, bp, E, T, T);
}

// round 5
// speedup vs baseline: 1.4775x; 1.4775x over previous
#include <cuda_runtime.h>
#include <cuda_fp16.h>
#include <cstdint>
#include <cstddef>

#define TT 8192
#define EE 4096

// ---------------- scratch (device globals) ----------------------------------
__device__ __half g_tokH[(size_t)TT * EE];   // tokens hi; later out [E,T] hi
__device__ __half g_tokL[(size_t)TT * EE];
__device__ __half g_wtH[(size_t)EE * EE];    // W^T hi (Wq/Wk/Wv sequentially)
__device__ __half g_wtL[(size_t)EE * EE];
__device__ __half g_wpH[(size_t)TT * TT];    // Wp^T hi (single-pass: no lo)
__device__ __half g_qtH[(size_t)EE * TT];    // q^T [E,T]
__device__ __half g_qtL[(size_t)EE * TT];
__device__ __half g_ktH[(size_t)EE * TT];
__device__ __half g_ktL[(size_t)EE * TT];
__device__ __half g_vH[(size_t)TT * EE];     // v [T,E] (single)
__device__ float  g_S[(size_t)EE * EE];      // logits fp32
__device__ __half g_attH[(size_t)EE * EE];   // att (single)

// ---------------- helpers ---------------------------------------------------
__device__ __forceinline__ uint32_t s2u(const void* p) {
    uint32_t a;
    asm("{ .reg .u64 t; cvta.to.shared.u64 t, %1; cvt.u32.u64 %0, t; }"
        : "=r"(a) : "l"(p));
    return a;
}
__device__ __forceinline__ void cp16(uint32_t dst, const void* src) {
    asm volatile("cp.async.cg.shared.global [%0], [%1], 16;"
                 :: "r"(dst), "l"(src));
}
#define CP_COMMIT() asm volatile("cp.async.commit_group;" ::: "memory")
#define CP_WAIT1()  asm volatile("cp.async.wait_group 1;" ::: "memory")

#define LDSM4(r, a)                                                          \
    asm volatile("ldmatrix.sync.aligned.m8n8.x4.shared.b16 "                 \
                 "{%0,%1,%2,%3}, [%4];"                                      \
                 : "=r"((r)[0]), "=r"((r)[1]), "=r"((r)[2]), "=r"((r)[3])    \
                 : "r"(a))

#define MMA16816(c, a, b0, b1)                                               \
    asm volatile("mma.sync.aligned.m16n8k16.row.col.f32.f16.f16.f32 "        \
                 "{%0,%1,%2,%3}, {%4,%5,%6,%7}, {%8,%9}, {%0,%1,%2,%3};"     \
                 : "+f"((c)[0]), "+f"((c)[1]), "+f"((c)[2]), "+f"((c)[3])    \
                 : "r"((a)[0]), "r"((a)[1]), "r"((a)[2]), "r"((a)[3]),       \
                   "r"(b0), "r"(b1))

__device__ __forceinline__ __half hhi(float v) { return __float2half(v); }
__device__ __forceinline__ __half hlo(float v, __half h) {
    return __float2half(v - __half2float(h));
}

// ---------------- split/single fp16 HMMA GEMM --------------------------------
// C[M,N] = sum_k A[m,k]*B[n,k]; K-major operands.
// SPLIT: 1 = hi/lo 3-pass (hh+hl+lh), 0 = hi-only single pass
// OUTM:  0 = fp32 out (Co), 1 = split half out (Co=hi, Col=lo), 2 = single half (Co)
// BIASM: 0 none, 1 per-col bias[n], 2 per-row bias[m]
#define BM 128
#define BN 256
#define BKT 32
#define PITCH 80
#define A_HL 10240          // 128 * 80
#define B_OFF 20480
#define B_HL 20480          // 256 * 80
#define STAGE 61440
#define NST 3

template <int SPLIT, int OUTM, int BIASM>
__global__ __launch_bounds__(256, 1)
void gemm_mma(const __half* __restrict__ Ah, const __half* __restrict__ Al,
              const __half* __restrict__ Bh, const __half* __restrict__ Bl,
              void* __restrict__ Co, void* __restrict__ Col,
              const float* __restrict__ bias,
              int M, int N, int K)
{
    extern __shared__ char dsm[];
    const uint32_t sb = s2u(dsm);

    const int tid  = threadIdx.x;
    const int wid  = tid >> 5;
    const int lane = tid & 31;
    const int bm = blockIdx.y * BM;
    const int bn = blockIdx.x * BN;
    const int m0 = (wid >> 2) * 64;
    const int n0 = (wid & 3) * 64;
    const int kt = K / BKT;

    auto load_stage = [&](int slot, int tile) {
        const uint32_t base = sb + slot * STAGE;
        const int k0 = tile * BKT;
        if (SPLIT) {
            #pragma unroll
            for (int j = 0; j < 12; j++) {
                int c = tid + j * 256;
                uint32_t dst;
                const __half* src;
                if (c < 1024) {
                    int hl = c >> 9, row = (c >> 2) & 127, ch = c & 3;
                    dst = base + hl * A_HL + row * PITCH + ch * 16;
                    const __half* p = hl ? Al : Ah;
                    src = p + (size_t)(bm + row) * K + k0 + ch * 8;
                } else {
                    int cc = c - 1024;
                    int hl = cc >> 10, row = (cc >> 2) & 255, ch = cc & 3;
                    dst = base + B_OFF + hl * B_HL + row * PITCH + ch * 16;
                    const __half* p = hl ? Bl : Bh;
                    src = p + (size_t)(bn + row) * K + k0 + ch * 8;
                }
                cp16(dst, src);
            }
        } else {
            #pragma unroll
            for (int j = 0; j < 6; j++) {
                int c = tid + j * 256;
                uint32_t dst;
                const __half* src;
                if (c < 512) {
                    int row = c >> 2, ch = c & 3;
                    dst = base + row * PITCH + ch * 16;
                    src = Ah + (size_t)(bm + row) * K + k0 + ch * 8;
                } else {
                    int cc = c - 512;
                    int row = cc >> 2, ch = cc & 3;
                    dst = base + B_OFF + row * PITCH + ch * 16;
                    src = Bh + (size_t)(bn + row) * K + k0 + ch * 8;
                }
                cp16(dst, src);
            }
        }
    };

    float acc[4][8][4];
    #pragma unroll
    for (int mt = 0; mt < 4; mt++)
        #pragma unroll
        for (int nt = 0; nt < 8; nt++)
            #pragma unroll
            for (int r = 0; r < 4; r++) acc[mt][nt][r] = 0.f;

    const uint32_t rowA = (uint32_t)(m0 + (lane & 15)) * PITCH + ((lane >> 4) << 4);
    const int quad = lane >> 3, rl = lane & 7;
    const uint32_t rowB = (uint32_t)(n0 + ((quad >> 1) << 3) + rl) * PITCH
                        + ((quad & 1) << 4);

    load_stage(0, 0); CP_COMMIT();
    if (kt > 1) load_stage(1, 1);
    CP_COMMIT();

    for (int i = 0; i < kt; i++) {
        CP_WAIT1();
        __syncthreads();
        const int nxt = i + NST - 1;
        if (nxt < kt) load_stage(nxt % NST, nxt);
        CP_COMMIT();

        const uint32_t base = sb + (i % NST) * STAGE;
        #pragma unroll
        for (int ks = 0; ks < 2; ks++) {
            const uint32_t ko = ks * 32;
            uint32_t ah[4][4], bh[4][4];
            #pragma unroll
            for (int mt = 0; mt < 4; mt++)
                LDSM4(ah[mt], base + rowA + mt * (16 * PITCH) + ko);
            #pragma unroll
            for (int np = 0; np < 4; np++)
                LDSM4(bh[np], base + B_OFF + rowB + np * (16 * PITCH) + ko);
            if (SPLIT) {
                uint32_t al[4][4], bl[4][4];
                #pragma unroll
                for (int mt = 0; mt < 4; mt++)
                    LDSM4(al[mt], base + A_HL + rowA + mt * (16 * PITCH) + ko);
                #pragma unroll
                for (int np = 0; np < 4; np++)
                    LDSM4(bl[np], base + B_OFF + B_HL + rowB + np * (16 * PITCH) + ko);
                #pragma unroll
                for (int mt = 0; mt < 4; mt++)
                    #pragma unroll
                    for (int nt = 0; nt < 8; nt++)
                        MMA16816(acc[mt][nt], ah[mt], bh[nt >> 1][(nt & 1) * 2],
                                 bh[nt >> 1][(nt & 1) * 2 + 1]);
                #pragma unroll
                for (int mt = 0; mt < 4; mt++)
                    #pragma unroll
                    for (int nt = 0; nt < 8; nt++)
                        MMA16816(acc[mt][nt], ah[mt], bl[nt >> 1][(nt & 1) * 2],
                                 bl[nt >> 1][(nt & 1) * 2 + 1]);
                #pragma unroll
                for (int mt = 0; mt < 4; mt++)
                    #pragma unroll
                    for (int nt = 0; nt < 8; nt++)
                        MMA16816(acc[mt][nt], al[mt], bh[nt >> 1][(nt & 1) * 2],
                                 bh[nt >> 1][(nt & 1) * 2 + 1]);
            } else {
                #pragma unroll
                for (int mt = 0; mt < 4; mt++)
                    #pragma unroll
                    for (int nt = 0; nt < 8; nt++)
                        MMA16816(acc[mt][nt], ah[mt], bh[nt >> 1][(nt & 1) * 2],
                                 bh[nt >> 1][(nt & 1) * 2 + 1]);
            }
        }
    }

    // ---- epilogue ----
    const int r1 = lane >> 2;
    const int cb = (lane & 3) * 2;
    float rbA[4], rbB[4];
    #pragma unroll
    for (int mt = 0; mt < 4; mt++) {
        if (BIASM == 2) {
            rbA[mt] = bias[bm + m0 + mt * 16 + r1];
            rbB[mt] = bias[bm + m0 + mt * 16 + r1 + 8];
        } else { rbA[mt] = 0.f; rbB[mt] = 0.f; }
    }
    #pragma unroll
    for (int nt = 0; nt < 8; nt++) {
        const int col = bn + n0 + nt * 8 + cb;
        float cb0 = 0.f, cb1 = 0.f;
        if (BIASM == 1) { cb0 = bias[col]; cb1 = bias[col + 1]; }
        #pragma unroll
        for (int mt = 0; mt < 4; mt++) {
            const int row = bm + m0 + mt * 16 + r1;
            float v0 = acc[mt][nt][0] + cb0 + rbA[mt];
            float v1 = acc[mt][nt][1] + cb1 + rbA[mt];
            float v2 = acc[mt][nt][2] + cb0 + rbB[mt];
            float v3 = acc[mt][nt][3] + cb1 + rbB[mt];
            if (OUTM == 0) {
                float* C = (float*)Co;
                *reinterpret_cast<float2*>(C + (size_t)row * N + col) =
                    make_float2(v0, v1);
                *reinterpret_cast<float2*>(C + (size_t)(row + 8) * N + col) =
                    make_float2(v2, v3);
            } else if (OUTM == 1) {
                __half* H = (__half*)Co;
                __half* L = (__half*)Col;
                __half2 h01, l01, h23, l23;
                h01.x = hhi(v0); h01.y = hhi(v1);
                l01.x = hlo(v0, h01.x); l01.y = hlo(v1, h01.y);
                h23.x = hhi(v2); h23.y = hhi(v3);
                l23.x = hlo(v2, h23.x); l23.y = hlo(v3, h23.y);
                *reinterpret_cast<__half2*>(H + (size_t)row * N + col) = h01;
                *reinterpret_cast<__half2*>(L + (size_t)row * N + col) = l01;
                *reinterpret_cast<__half2*>(H + (size_t)(row + 8) * N + col) = h23;
                *reinterpret_cast<__half2*>(L + (size_t)(row + 8) * N + col) = l23;
            } else {
                __half* H = (__half*)Co;
                __half2 h01, h23;
                h01.x = hhi(v0); h01.y = hhi(v1);
                h23.x = hhi(v2); h23.y = hhi(v3);
                *reinterpret_cast<__half2*>(H + (size_t)row * N + col) = h01;
                *reinterpret_cast<__half2*>(H + (size_t)(row + 8) * N + col) = h23;
            }
        }
    }
}

// ---------------- split / transpose preps ----------------------------------
__global__ void split_kernel(const float* __restrict__ in,
                             __half* __restrict__ oh,
                             __half* __restrict__ ol, size_t n4)
{
    size_t i = (size_t)blockIdx.x * 256 + threadIdx.x;
    if (i >= n4) return;
    float4 v = reinterpret_cast<const float4*>(in)[i];
    __half h0 = hhi(v.x), h1 = hhi(v.y), h2 = hhi(v.z), h3 = hhi(v.w);
    __half2 H0; H0.x = h0; H0.y = h1;
    __half2 H1; H1.x = h2; H1.y = h3;
    __half2 L0; L0.x = hlo(v.x, h0); L0.y = hlo(v.y, h1);
    __half2 L1; L1.x = hlo(v.z, h2); L1.y = hlo(v.w, h3);
    reinterpret_cast<__half2*>(oh)[2 * i]     = H0;
    reinterpret_cast<__half2*>(oh)[2 * i + 1] = H1;
    reinterpret_cast<__half2*>(ol)[2 * i]     = L0;
    reinterpret_cast<__half2*>(ol)[2 * i + 1] = L1;
}

// in [R,C] fp32 -> oh/ol [C,R] half (out[c][r] = in[r][c]); ol may be null
__global__ void splitT_kernel(const float* __restrict__ in,
                              __half* __restrict__ oh,
                              __half* __restrict__ ol, int R, int C)
{
    __shared__ float t[32][33];
    int x  = blockIdx.x * 32 + threadIdx.x;
    int y0 = blockIdx.y * 32;
    #pragma unroll
    for (int j = 0; j < 32; j += 8)
        t[threadIdx.y + j][threadIdx.x] = in[(size_t)(y0 + threadIdx.y + j) * C + x];
    __syncthreads();
    int ox  = y0 + threadIdx.x;
    int oy0 = blockIdx.x * 32;
    #pragma unroll
    for (int j = 0; j < 32; j += 8) {
        float v = t[threadIdx.x][threadIdx.y + j];
        __half h = hhi(v);
        size_t idx = (size_t)(oy0 + threadIdx.y + j) * R + ox;
        oh[idx] = h;
        if (ol != nullptr) ol[idx] = hlo(v, h);
    }
}

// ---------------- softmax -> single fp16 ------------------------------------
__global__ void softmax_half(const float* __restrict__ S,
                             __half* __restrict__ oh, int n)
{
    const int tid = threadIdx.x;
    const float* p = S + (size_t)blockIdx.x * n;
    float v[16];
    float m = -3.4e38f;
    #pragma unroll
    for (int i = 0; i < 16; i++) {
        v[i] = p[tid + (i << 8)];
        m = fmaxf(m, v[i]);
    }
    __shared__ float red[8];
    #pragma unroll
    for (int o = 16; o > 0; o >>= 1)
        m = fmaxf(m, __shfl_xor_sync(0xffffffffu, m, o));
    if ((tid & 31) == 0) red[tid >> 5] = m;
    __syncthreads();
    float M = red[0];
    #pragma unroll
    for (int i = 1; i < 8; i++) M = fmaxf(M, red[i]);

    float s = 0.f;
    #pragma unroll
    for (int i = 0; i < 16; i++) {
        v[i] = expf(v[i] - M);
        s += v[i];
    }
    __syncthreads();
    #pragma unroll
    for (int o = 16; o > 0; o >>= 1)
        s += __shfl_xor_sync(0xffffffffu, s, o);
    if ((tid & 31) == 0) red[tid >> 5] = s;
    __syncthreads();
    float tot = 0.f;
    #pragma unroll
    for (int i = 0; i < 8; i++) tot += red[i];
    const float inv = 1.0f / tot;

    __half* ph = oh + (size_t)blockIdx.x * n;
    #pragma unroll
    for (int i = 0; i < 16; i++)
        ph[tid + (i << 8)] = hhi(v[i] * inv);
}

// ---------------- host ------------------------------------------------------
extern "C" void kernel_launch(void* const* d_in, const int* in_sizes, int n_in,
                              void* d_out, int out_size)
{
    (void)in_sizes; (void)n_in; (void)out_size;
    const float* tokens = (const float*)d_in[0];
    const float* Wq = (const float*)d_in[1];
    const float* bq = (const float*)d_in[2];
    const float* Wk = (const float*)d_in[3];
    const float* bk = (const float*)d_in[4];
    const float* Wv = (const float*)d_in[5];
    const float* bv = (const float*)d_in[6];
    const float* Wp = (const float*)d_in[7];
    const float* bp = (const float*)d_in[8];
    float* out = (float*)d_out;

    __half *tokH, *tokL, *wtH, *wtL, *wpH;
    __half *qtH, *qtL, *ktH, *ktL, *vH, *attH;
    float *S;
    cudaGetSymbolAddress((void**)&tokH, g_tokH);
    cudaGetSymbolAddress((void**)&tokL, g_tokL);
    cudaGetSymbolAddress((void**)&wtH, g_wtH);
    cudaGetSymbolAddress((void**)&wtL, g_wtL);
    cudaGetSymbolAddress((void**)&wpH, g_wpH);
    cudaGetSymbolAddress((void**)&qtH, g_qtH);
    cudaGetSymbolAddress((void**)&qtL, g_qtL);
    cudaGetSymbolAddress((void**)&ktH, g_ktH);
    cudaGetSymbolAddress((void**)&ktL, g_ktL);
    cudaGetSymbolAddress((void**)&vH, g_vH);
    cudaGetSymbolAddress((void**)&attH, g_attH);
    cudaGetSymbolAddress((void**)&S, g_S);

    const int T = TT, E = EE;
    const size_t TE4 = (size_t)T * E / 4;

    static bool attr_set = false;
    if (!attr_set) {
        cudaFuncSetAttribute(gemm_mma<1, 1, 2>, cudaFuncAttributeMaxDynamicSharedMemorySize, NST * STAGE);
        cudaFuncSetAttribute(gemm_mma<0, 2, 1>, cudaFuncAttributeMaxDynamicSharedMemorySize, NST * STAGE);
        cudaFuncSetAttribute(gemm_mma<1, 0, 0>, cudaFuncAttributeMaxDynamicSharedMemorySize, NST * STAGE);
        cudaFuncSetAttribute(gemm_mma<0, 2, 0>, cudaFuncAttributeMaxDynamicSharedMemorySize, NST * STAGE);
        cudaFuncSetAttribute(gemm_mma<0, 0, 1>, cudaFuncAttributeMaxDynamicSharedMemorySize, NST * STAGE);
        attr_set = true;
    }
    const size_t smem = NST * STAGE;
    dim3 blkT(32, 8);

    // preps: split tokens; transpose Wp (hi only — final GEMM is single-pass)
    split_kernel<<<(unsigned)(TE4 / 256), 256>>>(tokens, tokH, tokL, TE4);
    splitT_kernel<<<dim3(T / 32, T / 32), blkT>>>(Wp, wpH, nullptr, T, T);

    // q^T [E,T] = Wq^T x tokens (split, row bias bq, split half out)
    splitT_kernel<<<dim3(E / 32, E / 32), blkT>>>(Wq, wtH, wtL, E, E);
    gemm_mma<1, 1, 2><<<dim3(T / BN, E / BM), 256, smem>>>(
        wtH, wtL, tokH, tokL, qtH, qtL, bq, E, T, E);

    // k^T [E,T]
    splitT_kernel<<<dim3(E / 32, E / 32), blkT>>>(Wk, wtH, wtL, E, E);
    gemm_mma<1, 1, 2><<<dim3(T / BN, E / BM), 256, smem>>>(
        wtH, wtL, tokH, tokL, ktH, ktL, bk, E, T, E);

    // v [T,E] = tokens x Wv^T (single-pass, col bias bv, single half out)
    splitT_kernel<<<dim3(E / 32, E / 32), blkT>>>(Wv, wtH, nullptr, E, E);
    gemm_mma<0, 2, 1><<<dim3(E / BN, T / BM), 256, smem>>>(
        tokH, nullptr, wtH, nullptr, vH, nullptr, bv, T, E, E);

    // logits S[E,E] = q^T k (split, fp32 out)
    gemm_mma<1, 0, 0><<<dim3(E / BN, E / BM), 256, smem>>>(
        qtH, qtL, ktH, ktL, S, nullptr, nullptr, E, E, T);

    // softmax rows -> single fp16 att
    softmax_half<<<E, 256>>>(S, attH, E);

    // out [E,T] = att @ v^T (single-pass, single half out -> tokH)
    gemm_mma<0, 2, 0><<<dim3(T / BN, E / BM), 256, smem>>>(
        attH, nullptr, vH, nullptr, tokH, nullptr, nullptr, E, T, E);

    // result [E,T] = out @ Wp + bp (single-pass, fp32 out, col bias bp)
    gemm_mma<0, 0, 1><<<dim3(T / BN, E / BM), 256, smem>>>(
        tokH, nullptr, wpH, nullptr, out, nullptr, bp, E, T, T);
}

// round 6
// speedup vs baseline: 1.6409x; 1.1106x over previous
#include <cuda_runtime.h>
#include <cuda_fp16.h>
#include <cstdint>
#include <cstddef>

#define TT 8192
#define EE 4096

// ---------------- scratch (device globals) ----------------------------------
__device__ __half g_tokH[(size_t)TT * EE];   // tokens hi; later out [E,T] hi
__device__ __half g_tokL[(size_t)TT * EE];
__device__ __half g_wtH[(size_t)EE * EE];    // W^T hi (Wq/Wk/Wv sequentially)
__device__ __half g_wtL[(size_t)EE * EE];
__device__ __half g_wpH[(size_t)TT * TT];    // Wp^T hi (single-pass: no lo)
__device__ __half g_qtH[(size_t)EE * TT];    // q^T [E,T]
__device__ __half g_qtL[(size_t)EE * TT];
__device__ __half g_ktH[(size_t)EE * TT];
__device__ __half g_ktL[(size_t)EE * TT];
__device__ __half g_vH[(size_t)TT * EE];     // v [T,E] (single)
__device__ float  g_S[(size_t)EE * EE];      // logits fp32
__device__ __half g_attH[(size_t)EE * EE];   // att (single)

// ---------------- helpers ---------------------------------------------------
__device__ __forceinline__ uint32_t s2u(const void* p) {
    uint32_t a;
    asm("{ .reg .u64 t; cvta.to.shared.u64 t, %1; cvt.u32.u64 %0, t; }"
        : "=r"(a) : "l"(p));
    return a;
}
__device__ __forceinline__ void cp16(uint32_t dst, const void* src) {
    asm volatile("cp.async.cg.shared.global [%0], [%1], 16;"
                 :: "r"(dst), "l"(src));
}
#define CP_COMMIT() asm volatile("cp.async.commit_group;" ::: "memory")
#define CP_WAIT1()  asm volatile("cp.async.wait_group 1;" ::: "memory")
#define CP_WAIT2()  asm volatile("cp.async.wait_group 2;" ::: "memory")

#define LDSM4(r, a)                                                          \
    asm volatile("ldmatrix.sync.aligned.m8n8.x4.shared.b16 "                 \
                 "{%0,%1,%2,%3}, [%4];"                                      \
                 : "=r"((r)[0]), "=r"((r)[1]), "=r"((r)[2]), "=r"((r)[3])    \
                 : "r"(a))

#define MMA16816(c, a, b0, b1)                                               \
    asm volatile("mma.sync.aligned.m16n8k16.row.col.f32.f16.f16.f32 "        \
                 "{%0,%1,%2,%3}, {%4,%5,%6,%7}, {%8,%9}, {%0,%1,%2,%3};"     \
                 : "+f"((c)[0]), "+f"((c)[1]), "+f"((c)[2]), "+f"((c)[3])    \
                 : "r"((a)[0]), "r"((a)[1]), "r"((a)[2]), "r"((a)[3]),       \
                   "r"(b0), "r"(b1))

__device__ __forceinline__ __half hhi(float v) { return __float2half(v); }
__device__ __forceinline__ __half hlo(float v, __half h) {
    return __float2half(v - __half2float(h));
}

// ================= split fp16 HMMA GEMM (hh+hl+lh) ==========================
// 256 threads, BM=128, BN=256, BKT=32, PITCH 80, 3 stages (unchanged R5 core).
#define BM 128
#define BN 256
#define BKT 32
#define PITCH 80
#define A_HL 10240
#define B_OFF 20480
#define B_HL 20480
#define STAGE 61440
#define NST 3

// OUTM: 0 = fp32 out, 1 = split half out. BIASM: 0 none, 2 per-row bias[m].
template <int OUTM, int BIASM>
__global__ __launch_bounds__(256, 1)
void gemm_mma(const __half* __restrict__ Ah, const __half* __restrict__ Al,
              const __half* __restrict__ Bh, const __half* __restrict__ Bl,
              void* __restrict__ Co, void* __restrict__ Col,
              const float* __restrict__ bias,
              int M, int N, int K)
{
    extern __shared__ char dsm[];
    const uint32_t sb = s2u(dsm);

    const int tid  = threadIdx.x;
    const int wid  = tid >> 5;
    const int lane = tid & 31;
    const int bm = blockIdx.y * BM;
    const int bn = blockIdx.x * BN;
    const int m0 = (wid >> 2) * 64;
    const int n0 = (wid & 3) * 64;
    const int kt = K / BKT;

    auto load_stage = [&](int slot, int tile) {
        const uint32_t base = sb + slot * STAGE;
        const int k0 = tile * BKT;
        #pragma unroll
        for (int j = 0; j < 12; j++) {
            int c = tid + j * 256;
            uint32_t dst;
            const __half* src;
            if (c < 1024) {
                int hl = c >> 9, row = (c >> 2) & 127, ch = c & 3;
                dst = base + hl * A_HL + row * PITCH + ch * 16;
                const __half* p = hl ? Al : Ah;
                src = p + (size_t)(bm + row) * K + k0 + ch * 8;
            } else {
                int cc = c - 1024;
                int hl = cc >> 10, row = (cc >> 2) & 255, ch = cc & 3;
                dst = base + B_OFF + hl * B_HL + row * PITCH + ch * 16;
                const __half* p = hl ? Bl : Bh;
                src = p + (size_t)(bn + row) * K + k0 + ch * 8;
            }
            cp16(dst, src);
        }
    };

    float acc[4][8][4];
    #pragma unroll
    for (int mt = 0; mt < 4; mt++)
        #pragma unroll
        for (int nt = 0; nt < 8; nt++)
            #pragma unroll
            for (int r = 0; r < 4; r++) acc[mt][nt][r] = 0.f;

    const uint32_t rowA = (uint32_t)(m0 + (lane & 15)) * PITCH + ((lane >> 4) << 4);
    const int quad = lane >> 3, rl = lane & 7;
    const uint32_t rowB = (uint32_t)(n0 + ((quad >> 1) << 3) + rl) * PITCH
                        + ((quad & 1) << 4);

    load_stage(0, 0); CP_COMMIT();
    if (kt > 1) load_stage(1, 1);
    CP_COMMIT();

    for (int i = 0; i < kt; i++) {
        CP_WAIT1();
        __syncthreads();
        const int nxt = i + NST - 1;
        if (nxt < kt) load_stage(nxt % NST, nxt);
        CP_COMMIT();

        const uint32_t base = sb + (i % NST) * STAGE;
        #pragma unroll
        for (int ks = 0; ks < 2; ks++) {
            const uint32_t ko = ks * 32;
            uint32_t ah[4][4], bh[4][4], al[4][4], bl[4][4];
            #pragma unroll
            for (int mt = 0; mt < 4; mt++)
                LDSM4(ah[mt], base + rowA + mt * (16 * PITCH) + ko);
            #pragma unroll
            for (int np = 0; np < 4; np++)
                LDSM4(bh[np], base + B_OFF + rowB + np * (16 * PITCH) + ko);
            #pragma unroll
            for (int mt = 0; mt < 4; mt++)
                LDSM4(al[mt], base + A_HL + rowA + mt * (16 * PITCH) + ko);
            #pragma unroll
            for (int np = 0; np < 4; np++)
                LDSM4(bl[np], base + B_OFF + B_HL + rowB + np * (16 * PITCH) + ko);
            #pragma unroll
            for (int mt = 0; mt < 4; mt++)
                #pragma unroll
                for (int nt = 0; nt < 8; nt++)
                    MMA16816(acc[mt][nt], ah[mt], bh[nt >> 1][(nt & 1) * 2],
                             bh[nt >> 1][(nt & 1) * 2 + 1]);
            #pragma unroll
            for (int mt = 0; mt < 4; mt++)
                #pragma unroll
                for (int nt = 0; nt < 8; nt++)
                    MMA16816(acc[mt][nt], ah[mt], bl[nt >> 1][(nt & 1) * 2],
                             bl[nt >> 1][(nt & 1) * 2 + 1]);
            #pragma unroll
            for (int mt = 0; mt < 4; mt++)
                #pragma unroll
                for (int nt = 0; nt < 8; nt++)
                    MMA16816(acc[mt][nt], al[mt], bh[nt >> 1][(nt & 1) * 2],
                             bh[nt >> 1][(nt & 1) * 2 + 1]);
        }
    }

    const int r1 = lane >> 2;
    const int cb = (lane & 3) * 2;
    float rbA[4], rbB[4];
    #pragma unroll
    for (int mt = 0; mt < 4; mt++) {
        if (BIASM == 2) {
            rbA[mt] = bias[bm + m0 + mt * 16 + r1];
            rbB[mt] = bias[bm + m0 + mt * 16 + r1 + 8];
        } else { rbA[mt] = 0.f; rbB[mt] = 0.f; }
    }
    #pragma unroll
    for (int nt = 0; nt < 8; nt++) {
        const int col = bn + n0 + nt * 8 + cb;
        #pragma unroll
        for (int mt = 0; mt < 4; mt++) {
            const int row = bm + m0 + mt * 16 + r1;
            float v0 = acc[mt][nt][0] + rbA[mt];
            float v1 = acc[mt][nt][1] + rbA[mt];
            float v2 = acc[mt][nt][2] + rbB[mt];
            float v3 = acc[mt][nt][3] + rbB[mt];
            if (OUTM == 0) {
                float* C = (float*)Co;
                *reinterpret_cast<float2*>(C + (size_t)row * N + col) =
                    make_float2(v0, v1);
                *reinterpret_cast<float2*>(C + (size_t)(row + 8) * N + col) =
                    make_float2(v2, v3);
            } else {
                __half* H = (__half*)Co;
                __half* L = (__half*)Col;
                __half2 h01, l01, h23, l23;
                h01.x = hhi(v0); h01.y = hhi(v1);
                l01.x = hlo(v0, h01.x); l01.y = hlo(v1, h01.y);
                h23.x = hhi(v2); h23.y = hhi(v3);
                l23.x = hlo(v2, h23.x); l23.y = hlo(v3, h23.y);
                *reinterpret_cast<__half2*>(H + (size_t)row * N + col) = h01;
                *reinterpret_cast<__half2*>(L + (size_t)row * N + col) = l01;
                *reinterpret_cast<__half2*>(H + (size_t)(row + 8) * N + col) = h23;
                *reinterpret_cast<__half2*>(L + (size_t)(row + 8) * N + col) = l23;
            }
        }
    }
}

// ================= single-pass fp16 HMMA GEMM (mem-bound path) ==============
// 512 threads (16 warps, warp tile 32x64), BKT=64, 4 stages, swizzled 128B rows.
#define SBKT 64
#define S_AOFF 0
#define S_BOFF 16384           // A: 128 rows x 128B
#define S_STAGE 49152          // + B: 256 rows x 128B
#define S_NST 4

// OUTM: 0 = fp32 out, 2 = single half out. BIASM: 0 none, 1 per-col bias[n].
template <int OUTM, int BIASM>
__global__ __launch_bounds__(512, 1)
void gemm_s(const __half* __restrict__ Ah, const __half* __restrict__ Bh,
            void* __restrict__ Co, const float* __restrict__ bias,
            int M, int N, int K)
{
    extern __shared__ char dsm[];
    const uint32_t sb = s2u(dsm);

    const int tid  = threadIdx.x;
    const int wid  = tid >> 5;
    const int lane = tid & 31;
    const int bm = blockIdx.y * BM;
    const int bn = blockIdx.x * BN;
    const int m0 = (wid >> 2) * 32;     // 16 warps: 4x4
    const int n0 = (wid & 3) * 64;
    const int kt = K / SBKT;

    // stage fill: 3072 x 16B chunks, 6 per thread; swizzle ch ^= row&7
    auto load_stage = [&](int slot, int tile) {
        const uint32_t base = sb + slot * S_STAGE;
        const int k0 = tile * SBKT;
        #pragma unroll
        for (int j = 0; j < 6; j++) {
            int c = tid + j * 512;
            uint32_t dst;
            const __half* src;
            if (c < 1024) {
                int row = c >> 3, ch = c & 7;
                dst = base + S_AOFF + row * 128 + ((ch ^ (row & 7)) << 4);
                src = Ah + (size_t)(bm + row) * K + k0 + ch * 8;
            } else {
                int cc = c - 1024;
                int row = cc >> 3, ch = cc & 7;
                dst = base + S_BOFF + row * 128 + ((ch ^ (row & 7)) << 4);
                src = Bh + (size_t)(bn + row) * K + k0 + ch * 8;
            }
            cp16(dst, src);
        }
    };

    float acc[2][8][4];
    #pragma unroll
    for (int mt = 0; mt < 2; mt++)
        #pragma unroll
        for (int nt = 0; nt < 8; nt++)
            #pragma unroll
            for (int r = 0; r < 4; r++) acc[mt][nt][r] = 0.f;

    // per-lane logical rows/chunk bases
    int rA[2], rB[4];
    #pragma unroll
    for (int mt = 0; mt < 2; mt++) rA[mt] = m0 + mt * 16 + (lane & 15);
    const int quad = lane >> 3, rl = lane & 7;
    #pragma unroll
    for (int np = 0; np < 4; np++) rB[np] = n0 + np * 16 + ((quad >> 1) << 3) + rl;
    const int cA = lane >> 4;       // chunk base for A
    const int cB = quad & 1;        // chunk base for B

    load_stage(0, 0); CP_COMMIT();
    load_stage(1, 1); CP_COMMIT();
    load_stage(2, 2); CP_COMMIT();

    for (int i = 0; i < kt; i++) {
        CP_WAIT2();
        __syncthreads();
        const int nxt = i + S_NST - 1;
        if (nxt < kt) load_stage(nxt & (S_NST - 1), nxt);
        CP_COMMIT();

        const uint32_t base = sb + (i & (S_NST - 1)) * S_STAGE;
        #pragma unroll
        for (int ks = 0; ks < 4; ks++) {
            uint32_t ah[2][4], bh[4][4];
            #pragma unroll
            for (int mt = 0; mt < 2; mt++) {
                int ch = (cA + 2 * ks) ^ (rA[mt] & 7);
                LDSM4(ah[mt], base + S_AOFF + rA[mt] * 128 + (ch << 4));
            }
            #pragma unroll
            for (int np = 0; np < 4; np++) {
                int ch = (cB + 2 * ks) ^ (rB[np] & 7);
                LDSM4(bh[np], base + S_BOFF + rB[np] * 128 + (ch << 4));
            }
            #pragma unroll
            for (int mt = 0; mt < 2; mt++)
                #pragma unroll
                for (int nt = 0; nt < 8; nt++)
                    MMA16816(acc[mt][nt], ah[mt], bh[nt >> 1][(nt & 1) * 2],
                             bh[nt >> 1][(nt & 1) * 2 + 1]);
        }
    }

    const int r1 = lane >> 2;
    const int cb = (lane & 3) * 2;
    #pragma unroll
    for (int nt = 0; nt < 8; nt++) {
        const int col = bn + n0 + nt * 8 + cb;
        float cb0 = 0.f, cb1 = 0.f;
        if (BIASM == 1) { cb0 = bias[col]; cb1 = bias[col + 1]; }
        #pragma unroll
        for (int mt = 0; mt < 2; mt++) {
            const int row = bm + m0 + mt * 16 + r1;
            float v0 = acc[mt][nt][0] + cb0;
            float v1 = acc[mt][nt][1] + cb1;
            float v2 = acc[mt][nt][2] + cb0;
            float v3 = acc[mt][nt][3] + cb1;
            if (OUTM == 0) {
                float* C = (float*)Co;
                *reinterpret_cast<float2*>(C + (size_t)row * N + col) =
                    make_float2(v0, v1);
                *reinterpret_cast<float2*>(C + (size_t)(row + 8) * N + col) =
                    make_float2(v2, v3);
            } else {
                __half* H = (__half*)Co;
                __half2 h01, h23;
                h01.x = hhi(v0); h01.y = hhi(v1);
                h23.x = hhi(v2); h23.y = hhi(v3);
                *reinterpret_cast<__half2*>(H + (size_t)row * N + col) = h01;
                *reinterpret_cast<__half2*>(H + (size_t)(row + 8) * N + col) = h23;
            }
        }
    }
}

// ---------------- split / transpose preps ----------------------------------
__global__ void split_kernel(const float* __restrict__ in,
                             __half* __restrict__ oh,
                             __half* __restrict__ ol, size_t n4)
{
    size_t i = (size_t)blockIdx.x * 256 + threadIdx.x;
    if (i >= n4) return;
    float4 v = reinterpret_cast<const float4*>(in)[i];
    __half h0 = hhi(v.x), h1 = hhi(v.y), h2 = hhi(v.z), h3 = hhi(v.w);
    __half2 H0; H0.x = h0; H0.y = h1;
    __half2 H1; H1.x = h2; H1.y = h3;
    __half2 L0; L0.x = hlo(v.x, h0); L0.y = hlo(v.y, h1);
    __half2 L1; L1.x = hlo(v.z, h2); L1.y = hlo(v.w, h3);
    reinterpret_cast<__half2*>(oh)[2 * i]     = H0;
    reinterpret_cast<__half2*>(oh)[2 * i + 1] = H1;
    reinterpret_cast<__half2*>(ol)[2 * i]     = L0;
    reinterpret_cast<__half2*>(ol)[2 * i + 1] = L1;
}

__global__ void splitT_kernel(const float* __restrict__ in,
                              __half* __restrict__ oh,
                              __half* __restrict__ ol, int R, int C)
{
    __shared__ float t[32][33];
    int x  = blockIdx.x * 32 + threadIdx.x;
    int y0 = blockIdx.y * 32;
    #pragma unroll
    for (int j = 0; j < 32; j += 8)
        t[threadIdx.y + j][threadIdx.x] = in[(size_t)(y0 + threadIdx.y + j) * C + x];
    __syncthreads();
    int ox  = y0 + threadIdx.x;
    int oy0 = blockIdx.x * 32;
    #pragma unroll
    for (int j = 0; j < 32; j += 8) {
        float v = t[threadIdx.x][threadIdx.y + j];
        __half h = hhi(v);
        size_t idx = (size_t)(oy0 + threadIdx.y + j) * R + ox;
        oh[idx] = h;
        if (ol != nullptr) ol[idx] = hlo(v, h);
    }
}

// ---------------- softmax -> single fp16 ------------------------------------
__global__ void softmax_half(const float* __restrict__ S,
                             __half* __restrict__ oh, int n)
{
    const int tid = threadIdx.x;
    const float* p = S + (size_t)blockIdx.x * n;
    float v[16];
    float m = -3.4e38f;
    #pragma unroll
    for (int i = 0; i < 16; i++) {
        v[i] = p[tid + (i << 8)];
        m = fmaxf(m, v[i]);
    }
    __shared__ float red[8];
    #pragma unroll
    for (int o = 16; o > 0; o >>= 1)
        m = fmaxf(m, __shfl_xor_sync(0xffffffffu, m, o));
    if ((tid & 31) == 0) red[tid >> 5] = m;
    __syncthreads();
    float M = red[0];
    #pragma unroll
    for (int i = 1; i < 8; i++) M = fmaxf(M, red[i]);

    float s = 0.f;
    #pragma unroll
    for (int i = 0; i < 16; i++) {
        v[i] = expf(v[i] - M);
        s += v[i];
    }
    __syncthreads();
    #pragma unroll
    for (int o = 16; o > 0; o >>= 1)
        s += __shfl_xor_sync(0xffffffffu, s, o);
    if ((tid & 31) == 0) red[tid >> 5] = s;
    __syncthreads();
    float tot = 0.f;
    #pragma unroll
    for (int i = 0; i < 8; i++) tot += red[i];
    const float inv = 1.0f / tot;

    __half* ph = oh + (size_t)blockIdx.x * n;
    #pragma unroll
    for (int i = 0; i < 16; i++)
        ph[tid + (i << 8)] = hhi(v[i] * inv);
}

// ---------------- host ------------------------------------------------------
extern "C" void kernel_launch(void* const* d_in, const int* in_sizes, int n_in,
                              void* d_out, int out_size)
{
    (void)in_sizes; (void)n_in; (void)out_size;
    const float* tokens = (const float*)d_in[0];
    const float* Wq = (const float*)d_in[1];
    const float* bq = (const float*)d_in[2];
    const float* Wk = (const float*)d_in[3];
    const float* bk = (const float*)d_in[4];
    const float* Wv = (const float*)d_in[5];
    const float* bv = (const float*)d_in[6];
    const float* Wp = (const float*)d_in[7];
    const float* bp = (const float*)d_in[8];
    float* out = (float*)d_out;

    __half *tokH, *tokL, *wtH, *wtL, *wpH;
    __half *qtH, *qtL, *ktH, *ktL, *vH, *attH;
    float *S;
    cudaGetSymbolAddress((void**)&tokH, g_tokH);
    cudaGetSymbolAddress((void**)&tokL, g_tokL);
    cudaGetSymbolAddress((void**)&wtH, g_wtH);
    cudaGetSymbolAddress((void**)&wtL, g_wtL);
    cudaGetSymbolAddress((void**)&wpH, g_wpH);
    cudaGetSymbolAddress((void**)&qtH, g_qtH);
    cudaGetSymbolAddress((void**)&qtL, g_qtL);
    cudaGetSymbolAddress((void**)&ktH, g_ktH);
    cudaGetSymbolAddress((void**)&ktL, g_ktL);
    cudaGetSymbolAddress((void**)&vH, g_vH);
    cudaGetSymbolAddress((void**)&attH, g_attH);
    cudaGetSymbolAddress((void**)&S, g_S);

    const int T = TT, E = EE;
    const size_t TE4 = (size_t)T * E / 4;

    static bool attr_set = false;
    if (!attr_set) {
        cudaFuncSetAttribute(gemm_mma<1, 2>, cudaFuncAttributeMaxDynamicSharedMemorySize, NST * STAGE);
        cudaFuncSetAttribute(gemm_mma<0, 0>, cudaFuncAttributeMaxDynamicSharedMemorySize, NST * STAGE);
        cudaFuncSetAttribute(gemm_s<2, 1>, cudaFuncAttributeMaxDynamicSharedMemorySize, S_NST * S_STAGE);
        cudaFuncSetAttribute(gemm_s<2, 0>, cudaFuncAttributeMaxDynamicSharedMemorySize, S_NST * S_STAGE);
        cudaFuncSetAttribute(gemm_s<0, 1>, cudaFuncAttributeMaxDynamicSharedMemorySize, S_NST * S_STAGE);
        attr_set = true;
    }
    const size_t smem  = NST * STAGE;
    const size_t smemS = S_NST * S_STAGE;
    dim3 blkT(32, 8);

    // preps
    split_kernel<<<(unsigned)(TE4 / 256), 256>>>(tokens, tokH, tokL, TE4);
    splitT_kernel<<<dim3(T / 32, T / 32), blkT>>>(Wp, wpH, nullptr, T, T);

    // q^T [E,T] = Wq^T x tokens (split, row bias bq, split half out)
    splitT_kernel<<<dim3(E / 32, E / 32), blkT>>>(Wq, wtH, wtL, E, E);
    gemm_mma<1, 2><<<dim3(T / BN, E / BM), 256, smem>>>(
        wtH, wtL, tokH, tokL, qtH, qtL, bq, E, T, E);

    // k^T [E,T]
    splitT_kernel<<<dim3(E / 32, E / 32), blkT>>>(Wk, wtH, wtL, E, E);
    gemm_mma<1, 2><<<dim3(T / BN, E / BM), 256, smem>>>(
        wtH, wtL, tokH, tokL, ktH, ktL, bk, E, T, E);

    // v [T,E] = tokens x Wv^T (single-pass, col bias bv)
    splitT_kernel<<<dim3(E / 32, E / 32), blkT>>>(Wv, wtH, nullptr, E, E);
    gemm_s<2, 1><<<dim3(E / BN, T / BM), 512, smemS>>>(
        tokH, wtH, vH, bv, T, E, E);

    // logits S[E,E] = q^T k (split, fp32 out)
    gemm_mma<0, 0><<<dim3(E / BN, E / BM), 256, smem>>>(
        qtH, qtL, ktH, ktL, S, nullptr, nullptr, E, E, T);

    // softmax rows -> single fp16 att
    softmax_half<<<E, 256>>>(S, attH, E);

    // out [E,T] = att @ v^T (single-pass) -> tokH
    gemm_s<2, 0><<<dim3(T / BN, E / BM), 512, smemS>>>(
        attH, vH, tokH, nullptr, E, T, E);

    // result [E,T] = out @ Wp + bp (single-pass, fp32 out, col bias bp)
    gemm_s<0, 1><<<dim3(T / BN, E / BM), 512, smemS>>>(
        tokH, wpH, out, bp, E, T, T);
}